// round 11
// baseline (speedup 1.0000x reference)
#include <cuda_runtime.h>
#include <cuda_fp16.h>
#include <stdint.h>

// ---------------------------------------------------------------------------
// out[b,t,u,o] = sum_h tanh(ep[b,t,h] + dp[b,u,h]) * W2[h,o] + b2[o]
//   ep = enc @ W1[:512],  dp = dec @ W1[512:] + b1
// enc (8,256,512) dec (8,64,512) W1 (1024,1024) b1 (1024) W2 (1024,128) b2 (128)
// out (8,256,64,128) fp32.  Base ISA only (mma.sync + cp.async + ldmatrix).
// ---------------------------------------------------------------------------

__device__ float   g_ep[2048 * 1024];          // enc proj fp32
__device__ __half  g_dph[512 * 1024];          // dec proj + b1, fp16
__device__ __half  g_ench[2048 * 512];         // enc fp16 (single)
__device__ __half  g_dech[512 * 512];          // dec fp16 (single)
__device__ __half  g_w1t_hi[2 * 1024 * 512];   // [part][n][k]
__device__ __half  g_w1t_lo[2 * 1024 * 512];
__device__ __half  g_w2t[128 * 1024];          // [n][k] = W2[k][n]

__device__ __forceinline__ uint32_t tanh2_fast(uint32_t x2) {   // half2 tanh
    uint32_t r; asm("tanh.approx.f16x2 %0, %1;" : "=r"(r) : "r"(x2)); return r;
}

__device__ __forceinline__ void mma_f16(float* c, const uint32_t* a, const uint32_t* b) {
    asm volatile("mma.sync.aligned.m16n8k16.row.col.f32.f16.f16.f32 "
        "{%0,%1,%2,%3}, {%4,%5,%6,%7}, {%8,%9}, {%0,%1,%2,%3};"
        : "+f"(c[0]), "+f"(c[1]), "+f"(c[2]), "+f"(c[3])
        : "r"(a[0]), "r"(a[1]), "r"(a[2]), "r"(a[3]), "r"(b[0]), "r"(b[1]));
}

__device__ __forceinline__ void ldsm4(uint32_t* r, uint32_t saddr) {
    asm volatile("ldmatrix.sync.aligned.m8n8.x4.shared.b16 {%0,%1,%2,%3}, [%4];"
        : "=r"(r[0]), "=r"(r[1]), "=r"(r[2]), "=r"(r[3]) : "r"(saddr));
}

__device__ __forceinline__ uint32_t smem_u32(const void* p) {
    return (uint32_t)__cvta_generic_to_shared(p);
}

__device__ __forceinline__ void cp16(void* sdst, const void* gsrc) {
    uint32_t s = (uint32_t)__cvta_generic_to_shared(sdst);
    asm volatile("cp.async.cg.shared.global [%0], [%1], 16;" :: "r"(s), "l"(gsrc) : "memory");
}
#define CP_COMMIT() asm volatile("cp.async.commit_group;" ::: "memory")
#define CP_WAIT0()  asm volatile("cp.async.wait_group 0;" ::: "memory")

// ---------------------------------------------------------------------------
// Merged prep: blocks [0,1024): enc+dec fp16 (4 elems/thread);
// [1024,2048): W1^T hi/lo; [2048,2176): W2^T fp16.
// ---------------------------------------------------------------------------
__global__ __launch_bounds__(256) void prep_all(const float* __restrict__ enc,
                                                const float* __restrict__ dec,
                                                const float* __restrict__ W1,
                                                const float* __restrict__ W2) {
    __shared__ float tile[32][33];
    int bid = blockIdx.x, tid = threadIdx.x;
    if (bid < 1024) {
        int i = bid * 256 + tid;       // float4 index
        {
            float4 v = *(const float4*)(enc + (size_t)i * 4);
            __half2 h0 = __floats2half2_rn(v.x, v.y);
            __half2 h1 = __floats2half2_rn(v.z, v.w);
            *(uint2*)&g_ench[(size_t)i * 4] = make_uint2(*(uint32_t*)&h0, *(uint32_t*)&h1);
        }
        if (i < 65536) {
            float4 v = *(const float4*)(dec + (size_t)i * 4);
            __half2 h0 = __floats2half2_rn(v.x, v.y);
            __half2 h1 = __floats2half2_rn(v.z, v.w);
            *(uint2*)&g_dech[(size_t)i * 4] = make_uint2(*(uint32_t*)&h0, *(uint32_t*)&h1);
        }
    } else if (bid < 2048) {
        int blk = bid - 1024;
        int tx = tid & 31, ty = tid >> 5;
        int bx = blk & 31, by = blk >> 5;       // n tile, k tile
        #pragma unroll
        for (int r = 0; r < 4; r++)
            tile[ty + r * 8][tx] = W1[(by * 32 + ty + r * 8) * 1024 + bx * 32 + tx];
        __syncthreads();
        #pragma unroll
        for (int r = 0; r < 4; r++) {
            int n  = bx * 32 + ty + r * 8;
            int kk = by * 32 + tx;
            float x = tile[tx][ty + r * 8];
            int p = kk >> 9;
            int idx = (p * 1024 + n) * 512 + (kk & 511);
            __half h = __float2half_rn(x);
            g_w1t_hi[idx] = h;
            g_w1t_lo[idx] = __float2half_rn(x - __half2float(h));
        }
    } else {
        int blk = bid - 2048;
        int tx = tid & 31, ty = tid >> 5;
        int bx = blk & 3, by = blk >> 2;        // n tile, k tile
        #pragma unroll
        for (int r = 0; r < 4; r++)
            tile[ty + r * 8][tx] = W2[(by * 32 + ty + r * 8) * 128 + bx * 32 + tx];
        __syncthreads();
        #pragma unroll
        for (int r = 0; r < 4; r++) {
            int n = bx * 32 + ty + r * 8;
            int k = by * 32 + tx;
            g_w2t[n * 1024 + k] = __float2half(tile[tx][ty + r * 8]);
        }
    }
}

// ---------------------------------------------------------------------------
// Projection (2-term: aH*bH + aH*bL).  256 CTAs, single wave at occ 2.
// bids 0..127:   enc tile 256x64 -> g_ep   (8 warps x (32 rows x 64 cols))
// bids 128..255: dec tile  64x64 -> g_dph  (4m x 2n warps, 16 rows x 32 cols)
// Stage: A (<=256 rows x 80B) @0 | Bh 64x80B @20480 | Bl @25600 = 30720 x2.
// ---------------------------------------------------------------------------
#define PROJ_STAGE 30720
#define PROJ_SMEM (2 * PROJ_STAGE)

__global__ __launch_bounds__(256, 2) void proj_kernel(const float* __restrict__ b1) {
    extern __shared__ char smem[];
    uint32_t sb = smem_u32(smem);

    int tid = threadIdx.x, wid = tid >> 5, lane = tid & 31;
    int gq = lane >> 2, tg = lane & 3;

    int id = blockIdx.x;
    bool isdec = id >= 128;
    int lid2 = isdec ? id - 128 : id;
    int tile_m = lid2 >> 4, tile_n = lid2 & 15;
    int m0 = tile_m * (isdec ? 64 : 256), n0 = tile_n * 64;
    int arows = isdec ? 64 : 256;

    const char* Ah = (const char*)(isdec ? g_dech : g_ench);
    const char* Bh = (const char*)(g_w1t_hi + (isdec ? 1024 * 512 : 0));
    const char* Bl = (const char*)(g_w1t_lo + (isdec ? 1024 * 512 : 0));

    auto issue = [&](int kc) {
        char* base = smem + (kc & 1) * PROJ_STAGE;
        int aiters = arows / 64;              // 4 for enc, 1 for dec
        for (int it = 0; it < aiters; it++) {
            int i = tid + it * 256;
            int r = i >> 2, sg = i & 3;
            size_t gsrc = (size_t)(m0 + r) * 1024 + kc * 64 + sg * 16;
            cp16(base + r * 80 + sg * 16, Ah + gsrc);
        }
        {
            int r = tid >> 2, sg = tid & 3;   // 64 rows x 4 segs
            size_t gsrc = (size_t)(n0 + r) * 1024 + kc * 64 + sg * 16;
            cp16(base + 20480 + r * 80 + sg * 16, Bh + gsrc);
            cp16(base + 25600 + r * 80 + sg * 16, Bl + gsrc);
        }
    };

    issue(0);
    CP_COMMIT();

    if (!isdec) {
        // ---------------- enc: warp = 32 rows x 64 cols ----------------
        uint32_t aOff = (uint32_t)(wid * 32 + ((lane >> 3) & 1) * 8 + (lane & 7)) * 80
                      + ((lane >> 4) & 1) * 16;
        uint32_t bOff = (uint32_t)(((lane >> 4) & 1) * 8 + (lane & 7)) * 80
                      + ((lane >> 3) & 1) * 16;

        float c[2][8][4];
        #pragma unroll
        for (int i = 0; i < 2; i++)
            #pragma unroll
            for (int j = 0; j < 8; j++)
                #pragma unroll
                for (int q = 0; q < 4; q++) c[i][j][q] = 0.f;

        for (int kc = 0; kc < 16; kc++) {
            CP_WAIT0();
            __syncthreads();
            if (kc + 1 < 16) { issue(kc + 1); CP_COMMIT(); }
            uint32_t base = sb + (kc & 1) * PROJ_STAGE;

            #pragma unroll
            for (int ks = 0; ks < 2; ks++) {
                uint32_t ko = ks * 32;
                uint32_t aH[2][4];
                #pragma unroll
                for (int mt = 0; mt < 2; mt++)
                    ldsm4(aH[mt], base + aOff + mt * 1280 + ko);
                #pragma unroll
                for (int p = 0; p < 4; p++) {
                    uint32_t bh[4], bl[4];
                    ldsm4(bh, base + 20480 + bOff + p * 1280 + ko);
                    ldsm4(bl, base + 25600 + bOff + p * 1280 + ko);
                    #pragma unroll
                    for (int mt = 0; mt < 2; mt++) {
                        mma_f16(c[mt][2 * p],     aH[mt], &bh[0]);
                        mma_f16(c[mt][2 * p],     aH[mt], &bl[0]);
                        mma_f16(c[mt][2 * p + 1], aH[mt], &bh[2]);
                        mma_f16(c[mt][2 * p + 1], aH[mt], &bl[2]);
                    }
                }
            }
        }

        #pragma unroll
        for (int mt = 0; mt < 2; mt++)
            #pragma unroll
            for (int nb = 0; nb < 8; nb++) {
                int col = n0 + nb * 8 + tg * 2;
                int row = m0 + wid * 32 + mt * 16 + gq;
                *(float2*)(g_ep + (size_t)row * 1024 + col) =
                    make_float2(c[mt][nb][0], c[mt][nb][1]);
                *(float2*)(g_ep + (size_t)(row + 8) * 1024 + col) =
                    make_float2(c[mt][nb][2], c[mt][nb][3]);
            }
    } else {
        // ---------------- dec: 4m x 2n warps, 16 rows x 32 cols ----------------
        int warp_m = wid >> 1, warp_n = wid & 1;
        uint32_t aOff = (uint32_t)(warp_m * 16 + ((lane >> 3) & 1) * 8 + (lane & 7)) * 80
                      + ((lane >> 4) & 1) * 16;
        uint32_t bOff = (uint32_t)(warp_n * 32 + ((lane >> 4) & 1) * 8 + (lane & 7)) * 80
                      + ((lane >> 3) & 1) * 16;

        float c[4][4];
        #pragma unroll
        for (int j = 0; j < 4; j++)
            #pragma unroll
            for (int q = 0; q < 4; q++) c[j][q] = 0.f;

        for (int kc = 0; kc < 16; kc++) {
            CP_WAIT0();
            __syncthreads();
            if (kc + 1 < 16) { issue(kc + 1); CP_COMMIT(); }
            uint32_t base = sb + (kc & 1) * PROJ_STAGE;

            #pragma unroll
            for (int ks = 0; ks < 2; ks++) {
                uint32_t ko = ks * 32;
                uint32_t aH[4];
                ldsm4(aH, base + aOff + ko);
                #pragma unroll
                for (int p = 0; p < 2; p++) {
                    uint32_t bh[4], bl[4];
                    ldsm4(bh, base + 20480 + bOff + p * 1280 + ko);
                    ldsm4(bl, base + 25600 + bOff + p * 1280 + ko);
                    mma_f16(c[2 * p],     aH, &bh[0]);
                    mma_f16(c[2 * p],     aH, &bl[0]);
                    mma_f16(c[2 * p + 1], aH, &bh[2]);
                    mma_f16(c[2 * p + 1], aH, &bl[2]);
                }
            }
        }

        #pragma unroll
        for (int nb = 0; nb < 4; nb++) {
            int col = n0 + warp_n * 32 + nb * 8 + tg * 2;
            int row = m0 + warp_m * 16 + gq;
            float bb0 = __ldg(b1 + col), bb1 = __ldg(b1 + col + 1);
            __half2 h0 = __floats2half2_rn(c[nb][0] + bb0, c[nb][1] + bb1);
            __half2 h1 = __floats2half2_rn(c[nb][2] + bb0, c[nb][3] + bb1);
            *(__half2*)(g_dph + (size_t)row * 1024 + col) = h0;
            *(__half2*)(g_dph + (size_t)(row + 8) * 1024 + col) = h1;
        }
    }
}

// ---------------------------------------------------------------------------
// Fused kernel: CTA = (batch b, 2 t, 64 u) -> M=128 x N=128, K=1024/64.
// Warps 4m x 2n, mt=2.  K-step software pipeline (A-frags ping-pong) with
// register-lean pair-level B prefetch (br[2][4] instead of br[2][16]) so the
// whole loop fits the 128-reg occ-2 budget without spills.
// smem: Bs 2x[128][72]h (36864) | dps 2x[64][72]h (18432) | sep [2][1024]f (8192)
// ---------------------------------------------------------------------------
#define FB_BS    0
#define FB_DPS   36864
#define FB_SEP   55296
#define FUSED_SMEM (55296 + 8192)

__global__ __launch_bounds__(256, 2) void fused_kernel(float* __restrict__ out,
                                                       const float* __restrict__ b2) {
    extern __shared__ char smem[];
    __half* Bs  = (__half*)(smem + FB_BS);     // [2][128][72]
    __half* dps = (__half*)(smem + FB_DPS);    // [2][64][72]
    float*  sep = (float*)(smem + FB_SEP);     // [2][1024]

    int tid = threadIdx.x, wid = tid >> 5, lane = tid & 31;
    int gq = lane >> 2, tg = lane & 3;
    int warp_m = wid >> 1, warp_n = wid & 1;

    int b  = blockIdx.x >> 7;
    int tp = blockIdx.x & 127;
    int t0 = tp * 2;

    // stage ep (2 x 1024 f32) once
    #pragma unroll
    for (int it = 0; it < 2; it++) {
        int i = tid + it * 256;
        int r = i >> 8, k = (i & 255) * 4;
        *(float4*)&sep[r * 1024 + k] =
            *(const float4*)(g_ep + (size_t)(b * 256 + t0 + r) * 1024 + k);
    }

    auto issue = [&](int kc) {
        int buf = kc & 1;
        #pragma unroll
        for (int it = 0; it < 4; it++) {     // Bs: 1024 segs of 16B
            int i = tid + it * 256;
            int r = i >> 3, sg = i & 7;
            cp16((char*)Bs + buf * 18432 + r * 144 + sg * 16,
                 (const char*)g_w2t + (size_t)r * 2048 + kc * 128 + sg * 16);
        }
        #pragma unroll
        for (int it = 0; it < 2; it++) {     // dps fp16: 512 segs of 16B
            int i = tid + it * 256;
            int u = i >> 3, sg = i & 7;
            cp16((char*)dps + buf * 9216 + u * 144 + sg * 16,
                 (const char*)g_dph + (size_t)(b * 64 + u) * 2048 + kc * 128 + sg * 16);
        }
    };

    int tl = warp_m >> 1;                 // t_local of this warp's rows
    int ub = (warp_m & 1) * 32;           // u base of this warp's rows

    uint32_t BsAddr = smem_u32(Bs);
    uint32_t bLane = (uint32_t)(((lane >> 4) & 1) * 8 + (lane & 7)) * 144
                   + ((lane >> 3) & 1) * 16;
    uint32_t baddr[4];
    #pragma unroll
    for (int p = 0; p < 4; p++)
        baddr[p] = BsAddr + (uint32_t)(warp_n * 64 + p * 16) * 144 + bLane;

    float c[2][8][4];
    #pragma unroll
    for (int i = 0; i < 2; i++)
        #pragma unroll
        for (int j = 0; j < 8; j++)
            #pragma unroll
            for (int q = 0; q < 4; q++) c[i][j][q] = 0.f;

    issue(0);
    CP_COMMIT();

    for (int kc = 0; kc < 16; kc++) {
        CP_WAIT0();
        __syncthreads();
        if (kc + 1 < 16) { issue(kc + 1); CP_COMMIT(); }

        int buf = kc & 1;
        const float*  ept = sep + tl * 1024 + kc * 64;
        const __half* dph = dps + buf * 4608;
        uint32_t bufoff = (uint32_t)buf * 18432;

        uint32_t areg[2][2][4];

        auto genA = [&](uint32_t (*ar)[4], int ks) {
            #pragma unroll
            for (int kp = 0; kp < 2; kp++) {
                int k = ks * 16 + tg * 2 + kp * 8;
                float2 e = *(const float2*)(ept + k);
                #pragma unroll
                for (int mt = 0; mt < 2; mt++) {
                    int u = ub + mt * 16 + gq;
                    __half2 da = *(const __half2*)(dph + u * 72 + k);
                    __half2 db = *(const __half2*)(dph + (u + 8) * 72 + k);
                    float2 fa = __half22float2(da);
                    float2 fb = __half22float2(db);
                    __half2 ha = __floats2half2_rn(e.x + fa.x, e.y + fa.y);
                    __half2 hb = __floats2half2_rn(e.x + fb.x, e.y + fb.y);
                    ar[mt][kp * 2 + 0] = tanh2_fast(*(uint32_t*)&ha);
                    ar[mt][kp * 2 + 1] = tanh2_fast(*(uint32_t*)&hb);
                }
            }
        };

        // prologue: A fragments for ks=0
        genA(areg[0], 0);

        #pragma unroll
        for (int ks = 0; ks < 4; ks++) {
            int cur = ks & 1;
            uint32_t br[2][4];
            // first B pair of this k-step
            ldsm4(br[0], baddr[0] + bufoff + ks * 32);
            // generate A frags for next k-step (covers br[0] latency)
            if (ks < 3) genA(areg[cur ^ 1], ks + 1);
            #pragma unroll
            for (int p = 0; p < 4; p++) {
                if (p < 3) ldsm4(br[(p + 1) & 1], baddr[p + 1] + bufoff + ks * 32);
                mma_f16(c[0][2 * p],     areg[cur][0], &br[p & 1][0]);
                mma_f16(c[0][2 * p + 1], areg[cur][0], &br[p & 1][2]);
                mma_f16(c[1][2 * p],     areg[cur][1], &br[p & 1][0]);
                mma_f16(c[1][2 * p + 1], areg[cur][1], &br[p & 1][2]);
            }
        }
    }

    // epilogue: global row = b*16384 + t0*64 + local (contiguous 128 rows)
    size_t orow0 = (size_t)b * 16384 + (size_t)t0 * 64;
    #pragma unroll
    for (int mt = 0; mt < 2; mt++) {
        int row0 = warp_m * 32 + mt * 16 + gq;
        #pragma unroll
        for (int nb = 0; nb < 8; nb++) {
            int col = warp_n * 64 + nb * 8 + tg * 2;
            float bb0 = __ldg(b2 + col);
            float bb1 = __ldg(b2 + col + 1);
            float2 v0 = make_float2(c[mt][nb][0] + bb0, c[mt][nb][1] + bb1);
            float2 v1 = make_float2(c[mt][nb][2] + bb0, c[mt][nb][3] + bb1);
            *(float2*)(out + (orow0 + row0) * 128 + col) = v0;
            *(float2*)(out + (orow0 + row0 + 8) * 128 + col) = v1;
        }
    }
}

// ---------------------------------------------------------------------------
extern "C" void kernel_launch(void* const* d_in, const int* in_sizes, int n_in,
                              void* d_out, int out_size) {
    const float* enc = (const float*)d_in[0];
    const float* dec = (const float*)d_in[1];
    const float* W1  = (const float*)d_in[2];
    const float* b1  = (const float*)d_in[3];
    const float* W2  = (const float*)d_in[4];
    const float* b2  = (const float*)d_in[5];
    float* out = (float*)d_out;

    cudaFuncSetAttribute(proj_kernel,  cudaFuncAttributeMaxDynamicSharedMemorySize, PROJ_SMEM);
    cudaFuncSetAttribute(fused_kernel, cudaFuncAttributeMaxDynamicSharedMemorySize, FUSED_SMEM);

    prep_all<<<2176, 256>>>(enc, dec, W1, W2);
    proj_kernel<<<256, 256, PROJ_SMEM>>>(b1);
    fused_kernel<<<1024, 256, FUSED_SMEM>>>(out, b2);
}

// round 12
// speedup vs baseline: 1.0647x; 1.0647x over previous
#include <cuda_runtime.h>
#include <cuda_fp16.h>
#include <stdint.h>

// ---------------------------------------------------------------------------
// out[b,t,u,o] = sum_h tanh(ep[b,t,h] + dp[b,u,h]) * W2[h,o] + b2[o]
//   ep = enc @ W1[:512],  dp = dec @ W1[512:] + b1
// enc (8,256,512) dec (8,64,512) W1 (1024,1024) b1 (1024) W2 (1024,128) b2 (128)
// out (8,256,64,128) fp32.  Base ISA only (mma.sync + cp.async + ldmatrix).
// ---------------------------------------------------------------------------

__device__ __half  g_eph[2048 * 1024];         // enc proj, fp16
__device__ __half  g_dph[512 * 1024];          // dec proj + b1, fp16
__device__ __half  g_ench[2048 * 512];         // enc fp16
__device__ __half  g_dech[512 * 512];          // dec fp16
__device__ __half  g_w1t_hi[2 * 1024 * 512];   // [part][n][k]
__device__ __half  g_w1t_lo[2 * 1024 * 512];
__device__ __half  g_w2t[128 * 1024];          // [n][k] = W2[k][n]

__device__ __forceinline__ uint32_t tanh2_fast(uint32_t x2) {   // half2 tanh
    uint32_t r; asm("tanh.approx.f16x2 %0, %1;" : "=r"(r) : "r"(x2)); return r;
}
__device__ __forceinline__ uint32_t hadd2(uint32_t a, uint32_t b) {
    uint32_t r; asm("add.f16x2 %0, %1, %2;" : "=r"(r) : "r"(a), "r"(b)); return r;
}

__device__ __forceinline__ void mma_f16(float* c, const uint32_t* a, const uint32_t* b) {
    asm volatile("mma.sync.aligned.m16n8k16.row.col.f32.f16.f16.f32 "
        "{%0,%1,%2,%3}, {%4,%5,%6,%7}, {%8,%9}, {%0,%1,%2,%3};"
        : "+f"(c[0]), "+f"(c[1]), "+f"(c[2]), "+f"(c[3])
        : "r"(a[0]), "r"(a[1]), "r"(a[2]), "r"(a[3]), "r"(b[0]), "r"(b[1]));
}

__device__ __forceinline__ void ldsm4(uint32_t* r, uint32_t saddr) {
    asm volatile("ldmatrix.sync.aligned.m8n8.x4.shared.b16 {%0,%1,%2,%3}, [%4];"
        : "=r"(r[0]), "=r"(r[1]), "=r"(r[2]), "=r"(r[3]) : "r"(saddr));
}

__device__ __forceinline__ uint32_t smem_u32(const void* p) {
    return (uint32_t)__cvta_generic_to_shared(p);
}

__device__ __forceinline__ void cp16(void* sdst, const void* gsrc) {
    uint32_t s = (uint32_t)__cvta_generic_to_shared(sdst);
    asm volatile("cp.async.cg.shared.global [%0], [%1], 16;" :: "r"(s), "l"(gsrc) : "memory");
}
#define CP_COMMIT() asm volatile("cp.async.commit_group;" ::: "memory")
#define CP_WAIT0()  asm volatile("cp.async.wait_group 0;" ::: "memory")

// ---------------------------------------------------------------------------
// Merged prep: blocks [0,1024): enc+dec fp16 (4 elems/thread);
// [1024,2048): W1^T hi/lo; [2048,2176): W2^T fp16.
// ---------------------------------------------------------------------------
__global__ __launch_bounds__(256) void prep_all(const float* __restrict__ enc,
                                                const float* __restrict__ dec,
                                                const float* __restrict__ W1,
                                                const float* __restrict__ W2) {
    __shared__ float tile[32][33];
    int bid = blockIdx.x, tid = threadIdx.x;
    if (bid < 1024) {
        int i = bid * 256 + tid;       // float4 index
        {
            float4 v = *(const float4*)(enc + (size_t)i * 4);
            __half2 h0 = __floats2half2_rn(v.x, v.y);
            __half2 h1 = __floats2half2_rn(v.z, v.w);
            *(uint2*)&g_ench[(size_t)i * 4] = make_uint2(*(uint32_t*)&h0, *(uint32_t*)&h1);
        }
        if (i < 65536) {
            float4 v = *(const float4*)(dec + (size_t)i * 4);
            __half2 h0 = __floats2half2_rn(v.x, v.y);
            __half2 h1 = __floats2half2_rn(v.z, v.w);
            *(uint2*)&g_dech[(size_t)i * 4] = make_uint2(*(uint32_t*)&h0, *(uint32_t*)&h1);
        }
    } else if (bid < 2048) {
        int blk = bid - 1024;
        int tx = tid & 31, ty = tid >> 5;
        int bx = blk & 31, by = blk >> 5;       // n tile, k tile
        #pragma unroll
        for (int r = 0; r < 4; r++)
            tile[ty + r * 8][tx] = W1[(by * 32 + ty + r * 8) * 1024 + bx * 32 + tx];
        __syncthreads();
        #pragma unroll
        for (int r = 0; r < 4; r++) {
            int n  = bx * 32 + ty + r * 8;
            int kk = by * 32 + tx;
            float x = tile[tx][ty + r * 8];
            int p = kk >> 9;
            int idx = (p * 1024 + n) * 512 + (kk & 511);
            __half h = __float2half_rn(x);
            g_w1t_hi[idx] = h;
            g_w1t_lo[idx] = __float2half_rn(x - __half2float(h));
        }
    } else {
        int blk = bid - 2048;
        int tx = tid & 31, ty = tid >> 5;
        int bx = blk & 3, by = blk >> 2;        // n tile, k tile
        #pragma unroll
        for (int r = 0; r < 4; r++)
            tile[ty + r * 8][tx] = W2[(by * 32 + ty + r * 8) * 128 + bx * 32 + tx];
        __syncthreads();
        #pragma unroll
        for (int r = 0; r < 4; r++) {
            int n = bx * 32 + ty + r * 8;
            int k = by * 32 + tx;
            g_w2t[n * 1024 + k] = __float2half(tile[tx][ty + r * 8]);
        }
    }
}

// ---------------------------------------------------------------------------
// Projection (2-term: aH*bH + aH*bL).  256 CTAs, single wave at occ 2.
// bids 0..127:   enc tile 256x64 -> g_eph (fp16)
// bids 128..255: dec tile  64x64 -> g_dph (fp16, +b1)
// Stage: A (<=256 rows x 80B) @0 | Bh 64x80B @20480 | Bl @25600 = 30720 x2.
// ---------------------------------------------------------------------------
#define PROJ_STAGE 30720
#define PROJ_SMEM (2 * PROJ_STAGE)

__global__ __launch_bounds__(256, 2) void proj_kernel(const float* __restrict__ b1) {
    extern __shared__ char smem[];
    uint32_t sb = smem_u32(smem);

    int tid = threadIdx.x, wid = tid >> 5, lane = tid & 31;
    int gq = lane >> 2, tg = lane & 3;

    int id = blockIdx.x;
    bool isdec = id >= 128;
    int lid2 = isdec ? id - 128 : id;
    int tile_m = lid2 >> 4, tile_n = lid2 & 15;
    int m0 = tile_m * (isdec ? 64 : 256), n0 = tile_n * 64;
    int arows = isdec ? 64 : 256;

    const char* Ah = (const char*)(isdec ? g_dech : g_ench);
    const char* Bh = (const char*)(g_w1t_hi + (isdec ? 1024 * 512 : 0));
    const char* Bl = (const char*)(g_w1t_lo + (isdec ? 1024 * 512 : 0));

    auto issue = [&](int kc) {
        char* base = smem + (kc & 1) * PROJ_STAGE;
        int aiters = arows / 64;              // 4 for enc, 1 for dec
        for (int it = 0; it < aiters; it++) {
            int i = tid + it * 256;
            int r = i >> 2, sg = i & 3;
            size_t gsrc = (size_t)(m0 + r) * 1024 + kc * 64 + sg * 16;
            cp16(base + r * 80 + sg * 16, Ah + gsrc);
        }
        {
            int r = tid >> 2, sg = tid & 3;   // 64 rows x 4 segs
            size_t gsrc = (size_t)(n0 + r) * 1024 + kc * 64 + sg * 16;
            cp16(base + 20480 + r * 80 + sg * 16, Bh + gsrc);
            cp16(base + 25600 + r * 80 + sg * 16, Bl + gsrc);
        }
    };

    issue(0);
    CP_COMMIT();

    if (!isdec) {
        // ---------------- enc: warp = 32 rows x 64 cols ----------------
        uint32_t aOff = (uint32_t)(wid * 32 + ((lane >> 3) & 1) * 8 + (lane & 7)) * 80
                      + ((lane >> 4) & 1) * 16;
        uint32_t bOff = (uint32_t)(((lane >> 4) & 1) * 8 + (lane & 7)) * 80
                      + ((lane >> 3) & 1) * 16;

        float c[2][8][4];
        #pragma unroll
        for (int i = 0; i < 2; i++)
            #pragma unroll
            for (int j = 0; j < 8; j++)
                #pragma unroll
                for (int q = 0; q < 4; q++) c[i][j][q] = 0.f;

        for (int kc = 0; kc < 16; kc++) {
            CP_WAIT0();
            __syncthreads();
            if (kc + 1 < 16) { issue(kc + 1); CP_COMMIT(); }
            uint32_t base = sb + (kc & 1) * PROJ_STAGE;

            #pragma unroll
            for (int ks = 0; ks < 2; ks++) {
                uint32_t ko = ks * 32;
                uint32_t aH[2][4];
                #pragma unroll
                for (int mt = 0; mt < 2; mt++)
                    ldsm4(aH[mt], base + aOff + mt * 1280 + ko);
                #pragma unroll
                for (int p = 0; p < 4; p++) {
                    uint32_t bh[4], bl[4];
                    ldsm4(bh, base + 20480 + bOff + p * 1280 + ko);
                    ldsm4(bl, base + 25600 + bOff + p * 1280 + ko);
                    #pragma unroll
                    for (int mt = 0; mt < 2; mt++) {
                        mma_f16(c[mt][2 * p],     aH[mt], &bh[0]);
                        mma_f16(c[mt][2 * p],     aH[mt], &bl[0]);
                        mma_f16(c[mt][2 * p + 1], aH[mt], &bh[2]);
                        mma_f16(c[mt][2 * p + 1], aH[mt], &bl[2]);
                    }
                }
            }
        }

        #pragma unroll
        for (int mt = 0; mt < 2; mt++)
            #pragma unroll
            for (int nb = 0; nb < 8; nb++) {
                int col = n0 + nb * 8 + tg * 2;
                int row = m0 + wid * 32 + mt * 16 + gq;
                __half2 h0 = __floats2half2_rn(c[mt][nb][0], c[mt][nb][1]);
                __half2 h1 = __floats2half2_rn(c[mt][nb][2], c[mt][nb][3]);
                *(__half2*)(g_eph + (size_t)row * 1024 + col) = h0;
                *(__half2*)(g_eph + (size_t)(row + 8) * 1024 + col) = h1;
            }
    } else {
        // ---------------- dec: 4m x 2n warps, 16 rows x 32 cols ----------------
        int warp_m = wid >> 1, warp_n = wid & 1;
        uint32_t aOff = (uint32_t)(warp_m * 16 + ((lane >> 3) & 1) * 8 + (lane & 7)) * 80
                      + ((lane >> 4) & 1) * 16;
        uint32_t bOff = (uint32_t)(warp_n * 32 + ((lane >> 4) & 1) * 8 + (lane & 7)) * 80
                      + ((lane >> 3) & 1) * 16;

        float c[4][4];
        #pragma unroll
        for (int j = 0; j < 4; j++)
            #pragma unroll
            for (int q = 0; q < 4; q++) c[j][q] = 0.f;

        for (int kc = 0; kc < 16; kc++) {
            CP_WAIT0();
            __syncthreads();
            if (kc + 1 < 16) { issue(kc + 1); CP_COMMIT(); }
            uint32_t base = sb + (kc & 1) * PROJ_STAGE;

            #pragma unroll
            for (int ks = 0; ks < 2; ks++) {
                uint32_t ko = ks * 32;
                uint32_t aH[4];
                ldsm4(aH, base + aOff + ko);
                #pragma unroll
                for (int p = 0; p < 2; p++) {
                    uint32_t bh[4], bl[4];
                    ldsm4(bh, base + 20480 + bOff + p * 1280 + ko);
                    ldsm4(bl, base + 25600 + bOff + p * 1280 + ko);
                    mma_f16(c[2 * p],     aH, &bh[0]);
                    mma_f16(c[2 * p],     aH, &bl[0]);
                    mma_f16(c[2 * p + 1], aH, &bh[2]);
                    mma_f16(c[2 * p + 1], aH, &bl[2]);
                }
            }
        }

        #pragma unroll
        for (int nb = 0; nb < 4; nb++) {
            int col = n0 + warp_n * 32 + nb * 8 + tg * 2;
            int row = m0 + warp_m * 16 + gq;
            float bb0 = __ldg(b1 + col), bb1 = __ldg(b1 + col + 1);
            __half2 h0 = __floats2half2_rn(c[nb][0] + bb0, c[nb][1] + bb1);
            __half2 h1 = __floats2half2_rn(c[nb][2] + bb0, c[nb][3] + bb1);
            *(__half2*)(g_dph + (size_t)row * 1024 + col) = h0;
            *(__half2*)(g_dph + (size_t)(row + 8) * 1024 + col) = h1;
        }
    }
}

// ---------------------------------------------------------------------------
// Fused kernel: CTA = (batch b, 2 t, 64 u) -> M=128 x N=128, K=1024/64.
// Warps 4m x 2n, mt=2.  K-step pipelined A-frags; pair-level B prefetch.
// A generation is pure fp16: LDS half2 + add.f16x2 + tanh.approx.f16x2.
// smem: Bs 2x[128][72]h (36864) | dps 2x[64][72]h (18432) | sep [2][1024]h (4096)
// ---------------------------------------------------------------------------
#define FB_BS    0
#define FB_DPS   36864
#define FB_SEP   55296
#define FUSED_SMEM (55296 + 4096)

__global__ __launch_bounds__(256, 2) void fused_kernel(float* __restrict__ out,
                                                       const float* __restrict__ b2) {
    extern __shared__ char smem[];
    __half* Bs  = (__half*)(smem + FB_BS);     // [2][128][72]
    __half* dps = (__half*)(smem + FB_DPS);    // [2][64][72]
    __half* sep = (__half*)(smem + FB_SEP);    // [2][1024]

    int tid = threadIdx.x, wid = tid >> 5, lane = tid & 31;
    int gq = lane >> 2, tg = lane & 3;
    int warp_m = wid >> 1, warp_n = wid & 1;

    int b  = blockIdx.x >> 7;
    int tp = blockIdx.x & 127;
    int t0 = tp * 2;

    // stage ep (2 x 1024 fp16) once: 256 threads x 8 halves
    {
        int r = tid >> 7, k = (tid & 127) * 8;
        *(uint4*)&sep[r * 1024 + k] =
            *(const uint4*)(g_eph + (size_t)(b * 256 + t0 + r) * 1024 + k);
    }

    auto issue = [&](int kc) {
        int buf = kc & 1;
        #pragma unroll
        for (int it = 0; it < 4; it++) {     // Bs: 1024 segs of 16B
            int i = tid + it * 256;
            int r = i >> 3, sg = i & 7;
            cp16((char*)Bs + buf * 18432 + r * 144 + sg * 16,
                 (const char*)g_w2t + (size_t)r * 2048 + kc * 128 + sg * 16);
        }
        #pragma unroll
        for (int it = 0; it < 2; it++) {     // dps fp16: 512 segs of 16B
            int i = tid + it * 256;
            int u = i >> 3, sg = i & 7;
            cp16((char*)dps + buf * 9216 + u * 144 + sg * 16,
                 (const char*)g_dph + (size_t)(b * 64 + u) * 2048 + kc * 128 + sg * 16);
        }
    };

    int tl = warp_m >> 1;                 // t_local of this warp's rows
    int ub = (warp_m & 1) * 32;           // u base of this warp's rows

    uint32_t BsAddr = smem_u32(Bs);
    uint32_t bLane = (uint32_t)(((lane >> 4) & 1) * 8 + (lane & 7)) * 144
                   + ((lane >> 3) & 1) * 16;
    uint32_t baddr[4];
    #pragma unroll
    for (int p = 0; p < 4; p++)
        baddr[p] = BsAddr + (uint32_t)(warp_n * 64 + p * 16) * 144 + bLane;

    float c[2][8][4];
    #pragma unroll
    for (int i = 0; i < 2; i++)
        #pragma unroll
        for (int j = 0; j < 8; j++)
            #pragma unroll
            for (int q = 0; q < 4; q++) c[i][j][q] = 0.f;

    issue(0);
    CP_COMMIT();

    for (int kc = 0; kc < 16; kc++) {
        CP_WAIT0();
        __syncthreads();
        if (kc + 1 < 16) { issue(kc + 1); CP_COMMIT(); }

        int buf = kc & 1;
        const __half* ept = sep + tl * 1024 + kc * 64;
        const __half* dph = dps + buf * 4608;
        uint32_t bufoff = (uint32_t)buf * 18432;

        uint32_t areg[2][2][4];

        // pure-fp16 A-frag generation: LDS + HADD2 + tanh2
        auto genA = [&](uint32_t (*ar)[4], int ks) {
            #pragma unroll
            for (int kp = 0; kp < 2; kp++) {
                int k = ks * 16 + tg * 2 + kp * 8;
                uint32_t e = *(const uint32_t*)(ept + k);
                #pragma unroll
                for (int mt = 0; mt < 2; mt++) {
                    int u = ub + mt * 16 + gq;
                    uint32_t da = *(const uint32_t*)(dph + u * 72 + k);
                    uint32_t db = *(const uint32_t*)(dph + (u + 8) * 72 + k);
                    ar[mt][kp * 2 + 0] = tanh2_fast(hadd2(e, da));
                    ar[mt][kp * 2 + 1] = tanh2_fast(hadd2(e, db));
                }
            }
        };

        // prologue: A fragments for ks=0
        genA(areg[0], 0);

        #pragma unroll
        for (int ks = 0; ks < 4; ks++) {
            int cur = ks & 1;
            uint32_t br[2][4];
            // first B pair of this k-step
            ldsm4(br[0], baddr[0] + bufoff + ks * 32);
            // generate A frags for next k-step (covers br[0] latency)
            if (ks < 3) genA(areg[cur ^ 1], ks + 1);
            #pragma unroll
            for (int p = 0; p < 4; p++) {
                if (p < 3) ldsm4(br[(p + 1) & 1], baddr[p + 1] + bufoff + ks * 32);
                mma_f16(c[0][2 * p],     areg[cur][0], &br[p & 1][0]);
                mma_f16(c[0][2 * p + 1], areg[cur][0], &br[p & 1][2]);
                mma_f16(c[1][2 * p],     areg[cur][1], &br[p & 1][0]);
                mma_f16(c[1][2 * p + 1], areg[cur][1], &br[p & 1][2]);
            }
        }
    }

    // epilogue: global row = b*16384 + t0*64 + local (contiguous 128 rows)
    size_t orow0 = (size_t)b * 16384 + (size_t)t0 * 64;
    #pragma unroll
    for (int mt = 0; mt < 2; mt++) {
        int row0 = warp_m * 32 + mt * 16 + gq;
        #pragma unroll
        for (int nb = 0; nb < 8; nb++) {
            int col = warp_n * 64 + nb * 8 + tg * 2;
            float bb0 = __ldg(b2 + col);
            float bb1 = __ldg(b2 + col + 1);
            float2 v0 = make_float2(c[mt][nb][0] + bb0, c[mt][nb][1] + bb1);
            float2 v1 = make_float2(c[mt][nb][2] + bb0, c[mt][nb][3] + bb1);
            *(float2*)(out + (orow0 + row0) * 128 + col) = v0;
            *(float2*)(out + (orow0 + row0 + 8) * 128 + col) = v1;
        }
    }
}

// ---------------------------------------------------------------------------
extern "C" void kernel_launch(void* const* d_in, const int* in_sizes, int n_in,
                              void* d_out, int out_size) {
    const float* enc = (const float*)d_in[0];
    const float* dec = (const float*)d_in[1];
    const float* W1  = (const float*)d_in[2];
    const float* b1  = (const float*)d_in[3];
    const float* W2  = (const float*)d_in[4];
    const float* b2  = (const float*)d_in[5];
    float* out = (float*)d_out;

    cudaFuncSetAttribute(proj_kernel,  cudaFuncAttributeMaxDynamicSharedMemorySize, PROJ_SMEM);
    cudaFuncSetAttribute(fused_kernel, cudaFuncAttributeMaxDynamicSharedMemorySize, FUSED_SMEM);

    prep_all<<<2176, 256>>>(enc, dec, W1, W2);
    proj_kernel<<<256, 256, PROJ_SMEM>>>(b1);
    fused_kernel<<<1024, 256, FUSED_SMEM>>>(out, b2);
}

// round 13
// speedup vs baseline: 1.0813x; 1.0157x over previous
#include <cuda_runtime.h>
#include <cuda_fp16.h>
#include <stdint.h>

// ---------------------------------------------------------------------------
// out[b,t,u,o] = sum_h tanh(ep[b,t,h] + dp[b,u,h]) * W2[h,o] + b2[o]
//   ep = enc @ W1[:512],  dp = dec @ W1[512:] + b1
// enc (8,256,512) dec (8,64,512) W1 (1024,1024) b1 (1024) W2 (1024,128) b2 (128)
// out (8,256,64,128) fp32.  Base ISA only (mma.sync + cp.async + ldmatrix).
// ---------------------------------------------------------------------------

__device__ __half  g_eph[2048 * 1024];         // enc proj, fp16
__device__ __half  g_dph[512 * 1024];          // dec proj + b1, fp16
__device__ __half  g_ench[2048 * 512];         // enc fp16
__device__ __half  g_dech[512 * 512];          // dec fp16
__device__ __half  g_w1t_hi[2 * 1024 * 512];   // [part][n][k]
__device__ __half  g_w1t_lo[2 * 1024 * 512];
__device__ __half  g_w2t[128 * 1024];          // [n][k] = W2[k][n]

__device__ __forceinline__ uint32_t tanh2_fast(uint32_t x2) {   // half2 tanh
    uint32_t r; asm("tanh.approx.f16x2 %0, %1;" : "=r"(r) : "r"(x2)); return r;
}
__device__ __forceinline__ uint32_t hadd2(uint32_t a, uint32_t b) {
    uint32_t r; asm("add.f16x2 %0, %1, %2;" : "=r"(r) : "r"(a), "r"(b)); return r;
}

__device__ __forceinline__ void mma_f16(float* c, const uint32_t* a, const uint32_t* b) {
    asm volatile("mma.sync.aligned.m16n8k16.row.col.f32.f16.f16.f32 "
        "{%0,%1,%2,%3}, {%4,%5,%6,%7}, {%8,%9}, {%0,%1,%2,%3};"
        : "+f"(c[0]), "+f"(c[1]), "+f"(c[2]), "+f"(c[3])
        : "r"(a[0]), "r"(a[1]), "r"(a[2]), "r"(a[3]), "r"(b[0]), "r"(b[1]));
}

__device__ __forceinline__ void ldsm4(uint32_t* r, uint32_t saddr) {
    asm volatile("ldmatrix.sync.aligned.m8n8.x4.shared.b16 {%0,%1,%2,%3}, [%4];"
        : "=r"(r[0]), "=r"(r[1]), "=r"(r[2]), "=r"(r[3]) : "r"(saddr));
}

__device__ __forceinline__ uint32_t smem_u32(const void* p) {
    return (uint32_t)__cvta_generic_to_shared(p);
}

__device__ __forceinline__ void cp16(void* sdst, const void* gsrc) {
    uint32_t s = (uint32_t)__cvta_generic_to_shared(sdst);
    asm volatile("cp.async.cg.shared.global [%0], [%1], 16;" :: "r"(s), "l"(gsrc) : "memory");
}
#define CP_COMMIT() asm volatile("cp.async.commit_group;" ::: "memory")
#define CP_WAIT0()  asm volatile("cp.async.wait_group 0;" ::: "memory")

// ---------------------------------------------------------------------------
// Merged prep: blocks [0,1024): enc+dec fp16 (4 elems/thread);
// [1024,2048): W1^T hi/lo; [2048,2176): W2^T fp16.
// ---------------------------------------------------------------------------
__global__ __launch_bounds__(256) void prep_all(const float* __restrict__ enc,
                                                const float* __restrict__ dec,
                                                const float* __restrict__ W1,
                                                const float* __restrict__ W2) {
    __shared__ float tile[32][33];
    int bid = blockIdx.x, tid = threadIdx.x;
    if (bid < 1024) {
        int i = bid * 256 + tid;       // float4 index
        {
            float4 v = *(const float4*)(enc + (size_t)i * 4);
            __half2 h0 = __floats2half2_rn(v.x, v.y);
            __half2 h1 = __floats2half2_rn(v.z, v.w);
            *(uint2*)&g_ench[(size_t)i * 4] = make_uint2(*(uint32_t*)&h0, *(uint32_t*)&h1);
        }
        if (i < 65536) {
            float4 v = *(const float4*)(dec + (size_t)i * 4);
            __half2 h0 = __floats2half2_rn(v.x, v.y);
            __half2 h1 = __floats2half2_rn(v.z, v.w);
            *(uint2*)&g_dech[(size_t)i * 4] = make_uint2(*(uint32_t*)&h0, *(uint32_t*)&h1);
        }
    } else if (bid < 2048) {
        int blk = bid - 1024;
        int tx = tid & 31, ty = tid >> 5;
        int bx = blk & 31, by = blk >> 5;       // n tile, k tile
        #pragma unroll
        for (int r = 0; r < 4; r++)
            tile[ty + r * 8][tx] = W1[(by * 32 + ty + r * 8) * 1024 + bx * 32 + tx];
        __syncthreads();
        #pragma unroll
        for (int r = 0; r < 4; r++) {
            int n  = bx * 32 + ty + r * 8;
            int kk = by * 32 + tx;
            float x = tile[tx][ty + r * 8];
            int p = kk >> 9;
            int idx = (p * 1024 + n) * 512 + (kk & 511);
            __half h = __float2half_rn(x);
            g_w1t_hi[idx] = h;
            g_w1t_lo[idx] = __float2half_rn(x - __half2float(h));
        }
    } else {
        int blk = bid - 2048;
        int tx = tid & 31, ty = tid >> 5;
        int bx = blk & 3, by = blk >> 2;        // n tile, k tile
        #pragma unroll
        for (int r = 0; r < 4; r++)
            tile[ty + r * 8][tx] = W2[(by * 32 + ty + r * 8) * 128 + bx * 32 + tx];
        __syncthreads();
        #pragma unroll
        for (int r = 0; r < 4; r++) {
            int n = bx * 32 + ty + r * 8;
            int k = by * 32 + tx;
            g_w2t[n * 1024 + k] = __float2half(tile[tx][ty + r * 8]);
        }
    }
}

// ---------------------------------------------------------------------------
// Projection (2-term: aH*bH + aH*bL).  256 CTAs, single wave at occ 2.
// bids 0..127:   enc tile 256x64 -> g_eph (fp16)
// bids 128..255: dec tile  64x64 -> g_dph (fp16, +b1)
// Stage: A (<=256 rows x 80B) @0 | Bh 64x80B @20480 | Bl @25600 = 30720 x2.
// ---------------------------------------------------------------------------
#define PROJ_STAGE 30720
#define PROJ_SMEM (2 * PROJ_STAGE)

__global__ __launch_bounds__(256, 2) void proj_kernel(const float* __restrict__ b1) {
    extern __shared__ char smem[];
    uint32_t sb = smem_u32(smem);

    int tid = threadIdx.x, wid = tid >> 5, lane = tid & 31;
    int gq = lane >> 2, tg = lane & 3;

    int id = blockIdx.x;
    bool isdec = id >= 128;
    int lid2 = isdec ? id - 128 : id;
    int tile_m = lid2 >> 4, tile_n = lid2 & 15;
    int m0 = tile_m * (isdec ? 64 : 256), n0 = tile_n * 64;
    int arows = isdec ? 64 : 256;

    const char* Ah = (const char*)(isdec ? g_dech : g_ench);
    const char* Bh = (const char*)(g_w1t_hi + (isdec ? 1024 * 512 : 0));
    const char* Bl = (const char*)(g_w1t_lo + (isdec ? 1024 * 512 : 0));

    auto issue = [&](int kc) {
        char* base = smem + (kc & 1) * PROJ_STAGE;
        int aiters = arows / 64;              // 4 for enc, 1 for dec
        for (int it = 0; it < aiters; it++) {
            int i = tid + it * 256;
            int r = i >> 2, sg = i & 3;
            size_t gsrc = (size_t)(m0 + r) * 1024 + kc * 64 + sg * 16;
            cp16(base + r * 80 + sg * 16, Ah + gsrc);
        }
        {
            int r = tid >> 2, sg = tid & 3;   // 64 rows x 4 segs
            size_t gsrc = (size_t)(n0 + r) * 1024 + kc * 64 + sg * 16;
            cp16(base + 20480 + r * 80 + sg * 16, Bh + gsrc);
            cp16(base + 25600 + r * 80 + sg * 16, Bl + gsrc);
        }
    };

    issue(0);
    CP_COMMIT();

    if (!isdec) {
        // ---------------- enc: warp = 32 rows x 64 cols ----------------
        uint32_t aOff = (uint32_t)(wid * 32 + ((lane >> 3) & 1) * 8 + (lane & 7)) * 80
                      + ((lane >> 4) & 1) * 16;
        uint32_t bOff = (uint32_t)(((lane >> 4) & 1) * 8 + (lane & 7)) * 80
                      + ((lane >> 3) & 1) * 16;

        float c[2][8][4];
        #pragma unroll
        for (int i = 0; i < 2; i++)
            #pragma unroll
            for (int j = 0; j < 8; j++)
                #pragma unroll
                for (int q = 0; q < 4; q++) c[i][j][q] = 0.f;

        for (int kc = 0; kc < 16; kc++) {
            CP_WAIT0();
            __syncthreads();
            if (kc + 1 < 16) { issue(kc + 1); CP_COMMIT(); }
            uint32_t base = sb + (kc & 1) * PROJ_STAGE;

            #pragma unroll
            for (int ks = 0; ks < 2; ks++) {
                uint32_t ko = ks * 32;
                uint32_t aH[2][4];
                #pragma unroll
                for (int mt = 0; mt < 2; mt++)
                    ldsm4(aH[mt], base + aOff + mt * 1280 + ko);
                #pragma unroll
                for (int p = 0; p < 4; p++) {
                    uint32_t bh[4], bl[4];
                    ldsm4(bh, base + 20480 + bOff + p * 1280 + ko);
                    ldsm4(bl, base + 25600 + bOff + p * 1280 + ko);
                    #pragma unroll
                    for (int mt = 0; mt < 2; mt++) {
                        mma_f16(c[mt][2 * p],     aH[mt], &bh[0]);
                        mma_f16(c[mt][2 * p],     aH[mt], &bl[0]);
                        mma_f16(c[mt][2 * p + 1], aH[mt], &bh[2]);
                        mma_f16(c[mt][2 * p + 1], aH[mt], &bl[2]);
                    }
                }
            }
        }

        #pragma unroll
        for (int mt = 0; mt < 2; mt++)
            #pragma unroll
            for (int nb = 0; nb < 8; nb++) {
                int col = n0 + nb * 8 + tg * 2;
                int row = m0 + wid * 32 + mt * 16 + gq;
                __half2 h0 = __floats2half2_rn(c[mt][nb][0], c[mt][nb][1]);
                __half2 h1 = __floats2half2_rn(c[mt][nb][2], c[mt][nb][3]);
                *(__half2*)(g_eph + (size_t)row * 1024 + col) = h0;
                *(__half2*)(g_eph + (size_t)(row + 8) * 1024 + col) = h1;
            }
    } else {
        // ---------------- dec: 4m x 2n warps, 16 rows x 32 cols ----------------
        int warp_m = wid >> 1, warp_n = wid & 1;
        uint32_t aOff = (uint32_t)(warp_m * 16 + ((lane >> 3) & 1) * 8 + (lane & 7)) * 80
                      + ((lane >> 4) & 1) * 16;
        uint32_t bOff = (uint32_t)(warp_n * 32 + ((lane >> 4) & 1) * 8 + (lane & 7)) * 80
                      + ((lane >> 3) & 1) * 16;

        float c[4][4];
        #pragma unroll
        for (int j = 0; j < 4; j++)
            #pragma unroll
            for (int q = 0; q < 4; q++) c[j][q] = 0.f;

        for (int kc = 0; kc < 16; kc++) {
            CP_WAIT0();
            __syncthreads();
            if (kc + 1 < 16) { issue(kc + 1); CP_COMMIT(); }
            uint32_t base = sb + (kc & 1) * PROJ_STAGE;

            #pragma unroll
            for (int ks = 0; ks < 2; ks++) {
                uint32_t ko = ks * 32;
                uint32_t aH[4];
                ldsm4(aH, base + aOff + ko);
                #pragma unroll
                for (int p = 0; p < 2; p++) {
                    uint32_t bh[4], bl[4];
                    ldsm4(bh, base + 20480 + bOff + p * 1280 + ko);
                    ldsm4(bl, base + 25600 + bOff + p * 1280 + ko);
                    mma_f16(c[2 * p],     aH, &bh[0]);
                    mma_f16(c[2 * p],     aH, &bl[0]);
                    mma_f16(c[2 * p + 1], aH, &bh[2]);
                    mma_f16(c[2 * p + 1], aH, &bl[2]);
                }
            }
        }

        #pragma unroll
        for (int nb = 0; nb < 4; nb++) {
            int col = n0 + warp_n * 32 + nb * 8 + tg * 2;
            int row = m0 + warp_m * 16 + gq;
            float bb0 = __ldg(b1 + col), bb1 = __ldg(b1 + col + 1);
            __half2 h0 = __floats2half2_rn(c[nb][0] + bb0, c[nb][1] + bb1);
            __half2 h1 = __floats2half2_rn(c[nb][2] + bb0, c[nb][3] + bb1);
            *(__half2*)(g_dph + (size_t)row * 1024 + col) = h0;
            *(__half2*)(g_dph + (size_t)(row + 8) * 1024 + col) = h1;
        }
    }
}

// ---------------------------------------------------------------------------
// Fused kernel: CTA = (batch b, 2 t, 64 u) -> M=128 x N=128, K=1024 in
// 8 chunks of 128 (half the barriers of the 64-chunk version).
// Warps 4m x 2n, mt=2.  K-step pipelined A-frags; pair-level B prefetch.
// A generation pure fp16: LDS half2 + add.f16x2 + tanh.approx.f16x2.
// smem: Bs 2x[128][136]h (69632) | dps 2x[64][136]h (34816) | sep [2][1024]h (4096)
// = 108544 B per CTA -> 2 CTAs/SM.
// ---------------------------------------------------------------------------
#define FB_BS    0
#define FB_DPS   69632
#define FB_SEP   104448
#define FUSED_SMEM 108544

__global__ __launch_bounds__(256, 2) void fused_kernel(float* __restrict__ out,
                                                       const float* __restrict__ b2) {
    extern __shared__ char smem[];
    __half* Bs  = (__half*)(smem + FB_BS);     // [2][128][136]
    __half* dps = (__half*)(smem + FB_DPS);    // [2][64][136]
    __half* sep = (__half*)(smem + FB_SEP);    // [2][1024]

    int tid = threadIdx.x, wid = tid >> 5, lane = tid & 31;
    int gq = lane >> 2, tg = lane & 3;
    int warp_m = wid >> 1, warp_n = wid & 1;

    int b  = blockIdx.x >> 7;
    int tp = blockIdx.x & 127;
    int t0 = tp * 2;

    // stage ep (2 x 1024 fp16) once: 256 threads x 8 halves
    {
        int r = tid >> 7, k = (tid & 127) * 8;
        *(uint4*)&sep[r * 1024 + k] =
            *(const uint4*)(g_eph + (size_t)(b * 256 + t0 + r) * 1024 + k);
    }

    auto issue = [&](int kc) {
        int buf = kc & 1;
        #pragma unroll
        for (int it = 0; it < 8; it++) {     // Bs: 128 rows x 16 segs of 16B
            int i = tid + it * 256;
            int r = i >> 4, sg = i & 15;
            cp16((char*)Bs + buf * 34816 + r * 272 + sg * 16,
                 (const char*)g_w2t + (size_t)r * 2048 + kc * 256 + sg * 16);
        }
        #pragma unroll
        for (int it = 0; it < 4; it++) {     // dps: 64 rows x 16 segs of 16B
            int i = tid + it * 256;
            int u = i >> 4, sg = i & 15;
            cp16((char*)dps + buf * 17408 + u * 272 + sg * 16,
                 (const char*)g_dph + (size_t)(b * 64 + u) * 2048 + kc * 256 + sg * 16);
        }
    };

    int tl = warp_m >> 1;                 // t_local of this warp's rows
    int ub = (warp_m & 1) * 32;           // u base of this warp's rows

    uint32_t BsAddr = smem_u32(Bs);
    uint32_t bLane = (uint32_t)(((lane >> 4) & 1) * 8 + (lane & 7)) * 272
                   + ((lane >> 3) & 1) * 16;
    uint32_t baddr[4];
    #pragma unroll
    for (int p = 0; p < 4; p++)
        baddr[p] = BsAddr + (uint32_t)(warp_n * 64 + p * 16) * 272 + bLane;

    float c[2][8][4];
    #pragma unroll
    for (int i = 0; i < 2; i++)
        #pragma unroll
        for (int j = 0; j < 8; j++)
            #pragma unroll
            for (int q = 0; q < 4; q++) c[i][j][q] = 0.f;

    issue(0);
    CP_COMMIT();

    for (int kc = 0; kc < 8; kc++) {
        CP_WAIT0();
        __syncthreads();
        if (kc + 1 < 8) { issue(kc + 1); CP_COMMIT(); }

        int buf = kc & 1;
        const __half* ept = sep + tl * 1024 + kc * 128;
        const __half* dph = dps + buf * 8704;
        uint32_t bufoff = (uint32_t)buf * 34816;

        uint32_t areg[2][2][4];

        // pure-fp16 A-frag generation: LDS + HADD2 + tanh2
        auto genA = [&](uint32_t (*ar)[4], int ks) {
            #pragma unroll
            for (int kp = 0; kp < 2; kp++) {
                int k = ks * 16 + tg * 2 + kp * 8;
                uint32_t e = *(const uint32_t*)(ept + k);
                #pragma unroll
                for (int mt = 0; mt < 2; mt++) {
                    int u = ub + mt * 16 + gq;
                    uint32_t da = *(const uint32_t*)(dph + u * 136 + k);
                    uint32_t db = *(const uint32_t*)(dph + (u + 8) * 136 + k);
                    ar[mt][kp * 2 + 0] = tanh2_fast(hadd2(e, da));
                    ar[mt][kp * 2 + 1] = tanh2_fast(hadd2(e, db));
                }
            }
        };

        // prologue: A fragments for ks=0
        genA(areg[0], 0);

        #pragma unroll
        for (int ks = 0; ks < 8; ks++) {
            int cur = ks & 1;
            uint32_t br[2][4];
            // first B pair of this k-step
            ldsm4(br[0], baddr[0] + bufoff + ks * 32);
            // generate A frags for next k-step (covers br[0] latency)
            if (ks < 7) genA(areg[cur ^ 1], ks + 1);
            #pragma unroll
            for (int p = 0; p < 4; p++) {
                if (p < 3) ldsm4(br[(p + 1) & 1], baddr[p + 1] + bufoff + ks * 32);
                mma_f16(c[0][2 * p],     areg[cur][0], &br[p & 1][0]);
                mma_f16(c[0][2 * p + 1], areg[cur][0], &br[p & 1][2]);
                mma_f16(c[1][2 * p],     areg[cur][1], &br[p & 1][0]);
                mma_f16(c[1][2 * p + 1], areg[cur][1], &br[p & 1][2]);
            }
        }
    }

    // epilogue: global row = b*16384 + t0*64 + local (contiguous 128 rows)
    size_t orow0 = (size_t)b * 16384 + (size_t)t0 * 64;
    #pragma unroll
    for (int mt = 0; mt < 2; mt++) {
        int row0 = warp_m * 32 + mt * 16 + gq;
        #pragma unroll
        for (int nb = 0; nb < 8; nb++) {
            int col = warp_n * 64 + nb * 8 + tg * 2;
            float bb0 = __ldg(b2 + col);
            float bb1 = __ldg(b2 + col + 1);
            float2 v0 = make_float2(c[mt][nb][0] + bb0, c[mt][nb][1] + bb1);
            float2 v1 = make_float2(c[mt][nb][2] + bb0, c[mt][nb][3] + bb1);
            *(float2*)(out + (orow0 + row0) * 128 + col) = v0;
            *(float2*)(out + (orow0 + row0 + 8) * 128 + col) = v1;
        }
    }
}

// ---------------------------------------------------------------------------
extern "C" void kernel_launch(void* const* d_in, const int* in_sizes, int n_in,
                              void* d_out, int out_size) {
    const float* enc = (const float*)d_in[0];
    const float* dec = (const float*)d_in[1];
    const float* W1  = (const float*)d_in[2];
    const float* b1  = (const float*)d_in[3];
    const float* W2  = (const float*)d_in[4];
    const float* b2  = (const float*)d_in[5];
    float* out = (float*)d_out;

    cudaFuncSetAttribute(proj_kernel,  cudaFuncAttributeMaxDynamicSharedMemorySize, PROJ_SMEM);
    cudaFuncSetAttribute(fused_kernel, cudaFuncAttributeMaxDynamicSharedMemorySize, FUSED_SMEM);

    prep_all<<<2176, 256>>>(enc, dec, W1, W2);
    proj_kernel<<<256, 256, PROJ_SMEM>>>(b1);
    fused_kernel<<<1024, 256, FUSED_SMEM>>>(out, b2);
}

// round 14
// speedup vs baseline: 1.1264x; 1.0417x over previous
#include <cuda_runtime.h>
#include <cuda_fp16.h>
#include <stdint.h>

// ---------------------------------------------------------------------------
// out[b,t,u,o] = sum_h tanh(ep[b,t,h] + dp[b,u,h]) * W2[h,o] + b2[o]
//   ep = enc @ W1[:512],  dp = dec @ W1[512:] + b1
// enc (8,256,512) dec (8,64,512) W1 (1024,1024) b1 (1024) W2 (1024,128) b2 (128)
// out (8,256,64,128) fp32.  Base ISA only (mma.sync + cp.async + ldmatrix).
// ---------------------------------------------------------------------------

__device__ __half  g_eph[2048 * 1024];         // enc proj, fp16
__device__ __half  g_dph[512 * 1024];          // dec proj + b1, fp16
__device__ __half  g_ench[2048 * 512];         // enc fp16
__device__ __half  g_dech[512 * 512];          // dec fp16
__device__ __half  g_w1t[2 * 1024 * 512];      // [part][n][k], fp16 single
__device__ __half  g_w2t[128 * 1024];          // [n][k] = W2[k][n]

__device__ __forceinline__ uint32_t tanh2_fast(uint32_t x2) {   // half2 tanh
    uint32_t r; asm("tanh.approx.f16x2 %0, %1;" : "=r"(r) : "r"(x2)); return r;
}
__device__ __forceinline__ uint32_t hadd2(uint32_t a, uint32_t b) {
    uint32_t r; asm("add.f16x2 %0, %1, %2;" : "=r"(r) : "r"(a), "r"(b)); return r;
}

__device__ __forceinline__ void mma_f16(float* c, const uint32_t* a, const uint32_t* b) {
    asm volatile("mma.sync.aligned.m16n8k16.row.col.f32.f16.f16.f32 "
        "{%0,%1,%2,%3}, {%4,%5,%6,%7}, {%8,%9}, {%0,%1,%2,%3};"
        : "+f"(c[0]), "+f"(c[1]), "+f"(c[2]), "+f"(c[3])
        : "r"(a[0]), "r"(a[1]), "r"(a[2]), "r"(a[3]), "r"(b[0]), "r"(b[1]));
}

__device__ __forceinline__ void ldsm4(uint32_t* r, uint32_t saddr) {
    asm volatile("ldmatrix.sync.aligned.m8n8.x4.shared.b16 {%0,%1,%2,%3}, [%4];"
        : "=r"(r[0]), "=r"(r[1]), "=r"(r[2]), "=r"(r[3]) : "r"(saddr));
}

__device__ __forceinline__ uint32_t smem_u32(const void* p) {
    return (uint32_t)__cvta_generic_to_shared(p);
}

__device__ __forceinline__ void cp16(void* sdst, const void* gsrc) {
    uint32_t s = (uint32_t)__cvta_generic_to_shared(sdst);
    asm volatile("cp.async.cg.shared.global [%0], [%1], 16;" :: "r"(s), "l"(gsrc) : "memory");
}
#define CP_COMMIT() asm volatile("cp.async.commit_group;" ::: "memory")
#define CP_WAIT0()  asm volatile("cp.async.wait_group 0;" ::: "memory")

// ---------------------------------------------------------------------------
// Merged prep: blocks [0,1024): enc+dec fp16 (4 elems/thread);
// [1024,2048): W1^T fp16 single; [2048,2176): W2^T fp16.
// ---------------------------------------------------------------------------
__global__ __launch_bounds__(256) void prep_all(const float* __restrict__ enc,
                                                const float* __restrict__ dec,
                                                const float* __restrict__ W1,
                                                const float* __restrict__ W2) {
    __shared__ float tile[32][33];
    int bid = blockIdx.x, tid = threadIdx.x;
    if (bid < 1024) {
        int i = bid * 256 + tid;       // float4 index
        {
            float4 v = *(const float4*)(enc + (size_t)i * 4);
            __half2 h0 = __floats2half2_rn(v.x, v.y);
            __half2 h1 = __floats2half2_rn(v.z, v.w);
            *(uint2*)&g_ench[(size_t)i * 4] = make_uint2(*(uint32_t*)&h0, *(uint32_t*)&h1);
        }
        if (i < 65536) {
            float4 v = *(const float4*)(dec + (size_t)i * 4);
            __half2 h0 = __floats2half2_rn(v.x, v.y);
            __half2 h1 = __floats2half2_rn(v.z, v.w);
            *(uint2*)&g_dech[(size_t)i * 4] = make_uint2(*(uint32_t*)&h0, *(uint32_t*)&h1);
        }
    } else if (bid < 2048) {
        int blk = bid - 1024;
        int tx = tid & 31, ty = tid >> 5;
        int bx = blk & 31, by = blk >> 5;       // n tile, k tile
        #pragma unroll
        for (int r = 0; r < 4; r++)
            tile[ty + r * 8][tx] = W1[(by * 32 + ty + r * 8) * 1024 + bx * 32 + tx];
        __syncthreads();
        #pragma unroll
        for (int r = 0; r < 4; r++) {
            int n  = bx * 32 + ty + r * 8;
            int kk = by * 32 + tx;
            float x = tile[tx][ty + r * 8];
            int p = kk >> 9;
            int idx = (p * 1024 + n) * 512 + (kk & 511);
            g_w1t[idx] = __float2half_rn(x);
        }
    } else {
        int blk = bid - 2048;
        int tx = tid & 31, ty = tid >> 5;
        int bx = blk & 3, by = blk >> 2;        // n tile, k tile
        #pragma unroll
        for (int r = 0; r < 4; r++)
            tile[ty + r * 8][tx] = W2[(by * 32 + ty + r * 8) * 128 + bx * 32 + tx];
        __syncthreads();
        #pragma unroll
        for (int r = 0; r < 4; r++) {
            int n = bx * 32 + ty + r * 8;
            int k = by * 32 + tx;
            g_w2t[n * 1024 + k] = __float2half(tile[tx][ty + r * 8]);
        }
    }
}

// ---------------------------------------------------------------------------
// Projection (single-term fp16).  256 CTAs, single wave at occ 2.
// bids 0..127:   enc tile 256x64 -> g_eph (fp16)
// bids 128..255: dec tile  64x64 -> g_dph (fp16, +b1)
// Stage: A (<=256 rows x 80B) @0 | B 64x80B @20480 = 25600 x2 stages.
// ---------------------------------------------------------------------------
#define PROJ_STAGE 25600
#define PROJ_SMEM (2 * PROJ_STAGE)

__global__ __launch_bounds__(256, 2) void proj_kernel(const float* __restrict__ b1) {
    extern __shared__ char smem[];
    uint32_t sb = smem_u32(smem);

    int tid = threadIdx.x, wid = tid >> 5, lane = tid & 31;
    int gq = lane >> 2, tg = lane & 3;

    int id = blockIdx.x;
    bool isdec = id >= 128;
    int lid2 = isdec ? id - 128 : id;
    int tile_m = lid2 >> 4, tile_n = lid2 & 15;
    int m0 = tile_m * (isdec ? 64 : 256), n0 = tile_n * 64;
    int arows = isdec ? 64 : 256;

    const char* Ah = (const char*)(isdec ? g_dech : g_ench);
    const char* Bh = (const char*)(g_w1t + (isdec ? 1024 * 512 : 0));

    auto issue = [&](int kc) {
        char* base = smem + (kc & 1) * PROJ_STAGE;
        int aiters = arows / 64;              // 4 for enc, 1 for dec
        for (int it = 0; it < aiters; it++) {
            int i = tid + it * 256;
            int r = i >> 2, sg = i & 3;
            size_t gsrc = (size_t)(m0 + r) * 1024 + kc * 64 + sg * 16;
            cp16(base + r * 80 + sg * 16, Ah + gsrc);
        }
        {
            int r = tid >> 2, sg = tid & 3;   // 64 rows x 4 segs
            size_t gsrc = (size_t)(n0 + r) * 1024 + kc * 64 + sg * 16;
            cp16(base + 20480 + r * 80 + sg * 16, Bh + gsrc);
        }
    };

    issue(0);
    CP_COMMIT();

    if (!isdec) {
        // ---------------- enc: warp = 32 rows x 64 cols ----------------
        uint32_t aOff = (uint32_t)(wid * 32 + ((lane >> 3) & 1) * 8 + (lane & 7)) * 80
                      + ((lane >> 4) & 1) * 16;
        uint32_t bOff = (uint32_t)(((lane >> 4) & 1) * 8 + (lane & 7)) * 80
                      + ((lane >> 3) & 1) * 16;

        float c[2][8][4];
        #pragma unroll
        for (int i = 0; i < 2; i++)
            #pragma unroll
            for (int j = 0; j < 8; j++)
                #pragma unroll
                for (int q = 0; q < 4; q++) c[i][j][q] = 0.f;

        for (int kc = 0; kc < 16; kc++) {
            CP_WAIT0();
            __syncthreads();
            if (kc + 1 < 16) { issue(kc + 1); CP_COMMIT(); }
            uint32_t base = sb + (kc & 1) * PROJ_STAGE;

            #pragma unroll
            for (int ks = 0; ks < 2; ks++) {
                uint32_t ko = ks * 32;
                uint32_t aH[2][4];
                #pragma unroll
                for (int mt = 0; mt < 2; mt++)
                    ldsm4(aH[mt], base + aOff + mt * 1280 + ko);
                #pragma unroll
                for (int p = 0; p < 4; p++) {
                    uint32_t bh[4];
                    ldsm4(bh, base + 20480 + bOff + p * 1280 + ko);
                    #pragma unroll
                    for (int mt = 0; mt < 2; mt++) {
                        mma_f16(c[mt][2 * p],     aH[mt], &bh[0]);
                        mma_f16(c[mt][2 * p + 1], aH[mt], &bh[2]);
                    }
                }
            }
        }

        #pragma unroll
        for (int mt = 0; mt < 2; mt++)
            #pragma unroll
            for (int nb = 0; nb < 8; nb++) {
                int col = n0 + nb * 8 + tg * 2;
                int row = m0 + wid * 32 + mt * 16 + gq;
                __half2 h0 = __floats2half2_rn(c[mt][nb][0], c[mt][nb][1]);
                __half2 h1 = __floats2half2_rn(c[mt][nb][2], c[mt][nb][3]);
                *(__half2*)(g_eph + (size_t)row * 1024 + col) = h0;
                *(__half2*)(g_eph + (size_t)(row + 8) * 1024 + col) = h1;
            }
    } else {
        // ---------------- dec: 4m x 2n warps, 16 rows x 32 cols ----------------
        int warp_m = wid >> 1, warp_n = wid & 1;
        uint32_t aOff = (uint32_t)(warp_m * 16 + ((lane >> 3) & 1) * 8 + (lane & 7)) * 80
                      + ((lane >> 4) & 1) * 16;
        uint32_t bOff = (uint32_t)(warp_n * 32 + ((lane >> 4) & 1) * 8 + (lane & 7)) * 80
                      + ((lane >> 3) & 1) * 16;

        float c[4][4];
        #pragma unroll
        for (int j = 0; j < 4; j++)
            #pragma unroll
            for (int q = 0; q < 4; q++) c[j][q] = 0.f;

        for (int kc = 0; kc < 16; kc++) {
            CP_WAIT0();
            __syncthreads();
            if (kc + 1 < 16) { issue(kc + 1); CP_COMMIT(); }
            uint32_t base = sb + (kc & 1) * PROJ_STAGE;

            #pragma unroll
            for (int ks = 0; ks < 2; ks++) {
                uint32_t ko = ks * 32;
                uint32_t aH[4];
                ldsm4(aH, base + aOff + ko);
                #pragma unroll
                for (int p = 0; p < 2; p++) {
                    uint32_t bh[4];
                    ldsm4(bh, base + 20480 + bOff + p * 1280 + ko);
                    mma_f16(c[2 * p],     aH, &bh[0]);
                    mma_f16(c[2 * p + 1], aH, &bh[2]);
                }
            }
        }

        #pragma unroll
        for (int nb = 0; nb < 4; nb++) {
            int col = n0 + warp_n * 32 + nb * 8 + tg * 2;
            int row = m0 + warp_m * 16 + gq;
            float bb0 = __ldg(b1 + col), bb1 = __ldg(b1 + col + 1);
            __half2 h0 = __floats2half2_rn(c[nb][0] + bb0, c[nb][1] + bb1);
            __half2 h1 = __floats2half2_rn(c[nb][2] + bb0, c[nb][3] + bb1);
            *(__half2*)(g_dph + (size_t)row * 1024 + col) = h0;
            *(__half2*)(g_dph + (size_t)(row + 8) * 1024 + col) = h1;
        }
    }
}

// ---------------------------------------------------------------------------
// Fused kernel: CTA = (batch b, 2 t, 64 u) -> M=128 x N=128, K=1024 in
// 8 chunks of 128.  Warps 4m x 2n, mt=2.  K-step pipelined A-frags;
// pair-level B prefetch.  genA pure fp16: LDS + add.f16x2 + tanh.approx.f16x2.
// smem: Bs 2x[128][136]h (69632) | dps 2x[64][136]h (34816) | sep [2][1024]h (4096)
// = 108544 B per CTA -> 2 CTAs/SM.
// ---------------------------------------------------------------------------
#define FB_BS    0
#define FB_DPS   69632
#define FB_SEP   104448
#define FUSED_SMEM 108544

__global__ __launch_bounds__(256, 2) void fused_kernel(float* __restrict__ out,
                                                       const float* __restrict__ b2) {
    extern __shared__ char smem[];
    __half* Bs  = (__half*)(smem + FB_BS);     // [2][128][136]
    __half* dps = (__half*)(smem + FB_DPS);    // [2][64][136]
    __half* sep = (__half*)(smem + FB_SEP);    // [2][1024]

    int tid = threadIdx.x, wid = tid >> 5, lane = tid & 31;
    int gq = lane >> 2, tg = lane & 3;
    int warp_m = wid >> 1, warp_n = wid & 1;

    int b  = blockIdx.x >> 7;
    int tp = blockIdx.x & 127;
    int t0 = tp * 2;

    // stage ep (2 x 1024 fp16) once: 256 threads x 8 halves
    {
        int r = tid >> 7, k = (tid & 127) * 8;
        *(uint4*)&sep[r * 1024 + k] =
            *(const uint4*)(g_eph + (size_t)(b * 256 + t0 + r) * 1024 + k);
    }

    auto issue = [&](int kc) {
        int buf = kc & 1;
        #pragma unroll
        for (int it = 0; it < 8; it++) {     // Bs: 128 rows x 16 segs of 16B
            int i = tid + it * 256;
            int r = i >> 4, sg = i & 15;
            cp16((char*)Bs + buf * 34816 + r * 272 + sg * 16,
                 (const char*)g_w2t + (size_t)r * 2048 + kc * 256 + sg * 16);
        }
        #pragma unroll
        for (int it = 0; it < 4; it++) {     // dps: 64 rows x 16 segs of 16B
            int i = tid + it * 256;
            int u = i >> 4, sg = i & 15;
            cp16((char*)dps + buf * 17408 + u * 272 + sg * 16,
                 (const char*)g_dph + (size_t)(b * 64 + u) * 2048 + kc * 256 + sg * 16);
        }
    };

    int tl = warp_m >> 1;                 // t_local of this warp's rows
    int ub = (warp_m & 1) * 32;           // u base of this warp's rows

    uint32_t BsAddr = smem_u32(Bs);
    uint32_t bLane = (uint32_t)(((lane >> 4) & 1) * 8 + (lane & 7)) * 272
                   + ((lane >> 3) & 1) * 16;
    uint32_t baddr[4];
    #pragma unroll
    for (int p = 0; p < 4; p++)
        baddr[p] = BsAddr + (uint32_t)(warp_n * 64 + p * 16) * 272 + bLane;

    float c[2][8][4];
    #pragma unroll
    for (int i = 0; i < 2; i++)
        #pragma unroll
        for (int j = 0; j < 8; j++)
            #pragma unroll
            for (int q = 0; q < 4; q++) c[i][j][q] = 0.f;

    issue(0);
    CP_COMMIT();

    for (int kc = 0; kc < 8; kc++) {
        CP_WAIT0();
        __syncthreads();
        if (kc + 1 < 8) { issue(kc + 1); CP_COMMIT(); }

        int buf = kc & 1;
        const __half* ept = sep + tl * 1024 + kc * 128;
        const __half* dph = dps + buf * 8704;
        uint32_t bufoff = (uint32_t)buf * 34816;

        uint32_t areg[2][2][4];

        // pure-fp16 A-frag generation: LDS + HADD2 + tanh2
        auto genA = [&](uint32_t (*ar)[4], int ks) {
            #pragma unroll
            for (int kp = 0; kp < 2; kp++) {
                int k = ks * 16 + tg * 2 + kp * 8;
                uint32_t e = *(const uint32_t*)(ept + k);
                #pragma unroll
                for (int mt = 0; mt < 2; mt++) {
                    int u = ub + mt * 16 + gq;
                    uint32_t da = *(const uint32_t*)(dph + u * 136 + k);
                    uint32_t db = *(const uint32_t*)(dph + (u + 8) * 136 + k);
                    ar[mt][kp * 2 + 0] = tanh2_fast(hadd2(e, da));
                    ar[mt][kp * 2 + 1] = tanh2_fast(hadd2(e, db));
                }
            }
        };

        // prologue: A fragments for ks=0
        genA(areg[0], 0);

        #pragma unroll
        for (int ks = 0; ks < 8; ks++) {
            int cur = ks & 1;
            uint32_t br[2][4];
            // first B pair of this k-step
            ldsm4(br[0], baddr[0] + bufoff + ks * 32);
            // generate A frags for next k-step (covers br[0] latency)
            if (ks < 7) genA(areg[cur ^ 1], ks + 1);
            #pragma unroll
            for (int p = 0; p < 4; p++) {
                if (p < 3) ldsm4(br[(p + 1) & 1], baddr[p + 1] + bufoff + ks * 32);
                mma_f16(c[0][2 * p],     areg[cur][0], &br[p & 1][0]);
                mma_f16(c[0][2 * p + 1], areg[cur][0], &br[p & 1][2]);
                mma_f16(c[1][2 * p],     areg[cur][1], &br[p & 1][0]);
                mma_f16(c[1][2 * p + 1], areg[cur][1], &br[p & 1][2]);
            }
        }
    }

    // epilogue: global row = b*16384 + t0*64 + local (contiguous 128 rows)
    size_t orow0 = (size_t)b * 16384 + (size_t)t0 * 64;
    #pragma unroll
    for (int mt = 0; mt < 2; mt++) {
        int row0 = warp_m * 32 + mt * 16 + gq;
        #pragma unroll
        for (int nb = 0; nb < 8; nb++) {
            int col = warp_n * 64 + nb * 8 + tg * 2;
            float bb0 = __ldg(b2 + col);
            float bb1 = __ldg(b2 + col + 1);
            float2 v0 = make_float2(c[mt][nb][0] + bb0, c[mt][nb][1] + bb1);
            float2 v1 = make_float2(c[mt][nb][2] + bb0, c[mt][nb][3] + bb1);
            *(float2*)(out + (orow0 + row0) * 128 + col) = v0;
            *(float2*)(out + (orow0 + row0 + 8) * 128 + col) = v1;
        }
    }
}

// ---------------------------------------------------------------------------
extern "C" void kernel_launch(void* const* d_in, const int* in_sizes, int n_in,
                              void* d_out, int out_size) {
    const float* enc = (const float*)d_in[0];
    const float* dec = (const float*)d_in[1];
    const float* W1  = (const float*)d_in[2];
    const float* b1  = (const float*)d_in[3];
    const float* W2  = (const float*)d_in[4];
    const float* b2  = (const float*)d_in[5];
    float* out = (float*)d_out;

    cudaFuncSetAttribute(proj_kernel,  cudaFuncAttributeMaxDynamicSharedMemorySize, PROJ_SMEM);
    cudaFuncSetAttribute(fused_kernel, cudaFuncAttributeMaxDynamicSharedMemorySize, FUSED_SMEM);

    prep_all<<<2176, 256>>>(enc, dec, W1, W2);
    proj_kernel<<<256, 256, PROJ_SMEM>>>(b1);
    fused_kernel<<<1024, 256, FUSED_SMEM>>>(out, b2);
}